// round 11
// baseline (speedup 1.0000x reference)
#include <cuda_runtime.h>
#include <math.h>
#include <stdint.h>

// Problem dims
#define BATCH 64
#define SEQLEN 256
#define DMODEL 256
#define DINNER 512
#define DSTATE 16
#define DTRANK 16
#define DCONV 4
#define DIMIN 256
#define DIMOUT 64
#define BL (BATCH * SEQLEN)      // 16384
#define SEG 8
#define LSEG (SEQLEN / SEG)      // 32
#define HSTATE 8                 // states per half-thread

// Scratch (device globals: no cudaMalloc allowed)
__device__ float g_xin[BL * DINNER];
__device__ float g_z[BL * DINNER];
__device__ float g_xc[BL * DINNER];
__device__ float g_delta[BL * DINNER];
__device__ float g_Bm[BL * DSTATE];
__device__ float g_Cm[BL * DSTATE];
__device__ float g_ybar[BATCH * DINNER];
// segment scan partials
__device__ float g_segW[SEG * BATCH * DINNER * DSTATE];
__device__ float g_segP[SEG * BATCH * DINNER * DSTATE];
__device__ float g_segV[SEG * BATCH * DINNER * DSTATE];
__device__ float g_segc[SEG * BATCH * DINNER];

// ---------------------------------------------------------------------------
// K1: xz = input @ W_in^T via tf32 tensor-core mma (R9-proven, verbatim).
// ---------------------------------------------------------------------------
__device__ __forceinline__ uint32_t f2tf32(float x) {
    uint32_t u;
    asm("cvt.rna.tf32.f32 %0, %1;" : "=r"(u) : "f"(x));
    return u;
}

__global__ __launch_bounds__(256) void k1_gemm(const float* __restrict__ X,
                                               const float* __restrict__ W) {
    __shared__ uint32_t Xs[128][36];
    __shared__ uint32_t Ws[128][36];

    const int m0 = blockIdx.y * 128;
    const int n0 = blockIdx.x * 128;
    const int tid = threadIdx.x;
    const int wid = tid >> 5;
    const int lane = tid & 31;
    const int warp_m = wid & 1;
    const int warp_n = wid >> 1;
    const int g = lane >> 2;
    const int tig = lane & 3;

    float c[4][4][4];
#pragma unroll
    for (int ma = 0; ma < 4; ma++)
#pragma unroll
        for (int na = 0; na < 4; na++)
#pragma unroll
            for (int q = 0; q < 4; q++) c[ma][na][q] = 0.f;

    const int lrow = tid >> 1;
    const int lc4 = (tid & 1) * 16;

#pragma unroll 1
    for (int chunk = 0; chunk < 8; chunk++) {
        const int k0 = chunk * 32;
#pragma unroll
        for (int i = 0; i < 4; i++) {
            float4 v = *reinterpret_cast<const float4*>(&X[(size_t)(m0 + lrow) * 256 + k0 + lc4 + i * 4]);
            Xs[lrow][lc4 + i * 4 + 0] = f2tf32(v.x);
            Xs[lrow][lc4 + i * 4 + 1] = f2tf32(v.y);
            Xs[lrow][lc4 + i * 4 + 2] = f2tf32(v.z);
            Xs[lrow][lc4 + i * 4 + 3] = f2tf32(v.w);
            float4 w = *reinterpret_cast<const float4*>(&W[(size_t)(n0 + lrow) * 256 + k0 + lc4 + i * 4]);
            Ws[lrow][lc4 + i * 4 + 0] = f2tf32(w.x);
            Ws[lrow][lc4 + i * 4 + 1] = f2tf32(w.y);
            Ws[lrow][lc4 + i * 4 + 2] = f2tf32(w.z);
            Ws[lrow][lc4 + i * 4 + 3] = f2tf32(w.w);
        }
        __syncthreads();

#pragma unroll
        for (int ks = 0; ks < 4; ks++) {
            const int kk = ks * 8;
            uint32_t a[4][4];
#pragma unroll
            for (int ma = 0; ma < 4; ma++) {
                const int ar = warp_m * 64 + ma * 16 + g;
                a[ma][0] = Xs[ar][kk + tig];
                a[ma][1] = Xs[ar + 8][kk + tig];
                a[ma][2] = Xs[ar][kk + tig + 4];
                a[ma][3] = Xs[ar + 8][kk + tig + 4];
            }
            uint32_t bfr[4][2];
#pragma unroll
            for (int na = 0; na < 4; na++) {
                const int br = warp_n * 32 + na * 8 + g;
                bfr[na][0] = Ws[br][kk + tig];
                bfr[na][1] = Ws[br][kk + tig + 4];
            }
#pragma unroll
            for (int ma = 0; ma < 4; ma++)
#pragma unroll
                for (int na = 0; na < 4; na++) {
                    asm volatile(
                        "mma.sync.aligned.m16n8k8.row.col.f32.tf32.tf32.f32 "
                        "{%0,%1,%2,%3}, {%4,%5,%6,%7}, {%8,%9}, {%0,%1,%2,%3};"
                        : "+f"(c[ma][na][0]), "+f"(c[ma][na][1]),
                          "+f"(c[ma][na][2]), "+f"(c[ma][na][3])
                        : "r"(a[ma][0]), "r"(a[ma][1]), "r"(a[ma][2]), "r"(a[ma][3]),
                          "r"(bfr[na][0]), "r"(bfr[na][1]));
                }
        }
        __syncthreads();
    }

    float* dstbase = (n0 < DINNER) ? g_xin : g_z;
    const int nbase = (n0 < DINNER) ? n0 : (n0 - DINNER);
#pragma unroll
    for (int ma = 0; ma < 4; ma++) {
        const int m = m0 + warp_m * 64 + ma * 16 + g;
#pragma unroll
        for (int na = 0; na < 4; na++) {
            const int n = nbase + warp_n * 32 + na * 8 + tig * 2;
            *reinterpret_cast<float2*>(&dstbase[(size_t)m * DINNER + n]) =
                make_float2(c[ma][na][0], c[ma][na][1]);
            *reinterpret_cast<float2*>(&dstbase[(size_t)(m + 8) * DINNER + n]) =
                make_float2(c[ma][na][2], c[ma][na][3]);
        }
    }
}

// ---------------------------------------------------------------------------
// K3 (fused conv + 8-row proj)  (R9-proven)
// ---------------------------------------------------------------------------
#define K3ROWS 8
__global__ __launch_bounds__(512) void k3_convproj(const float* __restrict__ cw,
                                                   const float* __restrict__ cb,
                                                   const float* __restrict__ Wx,
                                                   const float* __restrict__ Wdt,
                                                   const float* __restrict__ bdt) {
    const int bl0 = blockIdx.x * K3ROWS;
    const int l0 = bl0 & (SEQLEN - 1);
    __shared__ float sx[K3ROWS + 3][DINNER];
    __shared__ float sdbl[K3ROWS][48];
    const int tid = threadIdx.x;

#pragma unroll
    for (int j = 0; j < K3ROWS + 3; j++) {
        int bl = bl0 - 3 + j;
        sx[j][tid] = (l0 + j >= 3) ? g_xin[(size_t)bl * DINNER + tid] : 0.f;
    }

    const float w0 = cw[tid * 4 + 0], w1 = cw[tid * 4 + 1];
    const float w2 = cw[tid * 4 + 2], w3 = cw[tid * 4 + 3];
    const float bias = cb[tid];
#pragma unroll
    for (int r = 0; r < K3ROWS; r++) {
        float sum = bias;
        sum = fmaf(sx[r + 0][tid], w0, sum);
        sum = fmaf(sx[r + 1][tid], w1, sum);
        sum = fmaf(sx[r + 2][tid], w2, sum);
        sum = fmaf(sx[r + 3][tid], w3, sum);
        float xc = sum / (1.f + expf(-sum));
        sx[r][tid] = xc;
        g_xc[(size_t)(bl0 + r) * DINNER + tid] = xc;
    }
    __syncthreads();

    const int w = tid >> 5, lane = tid & 31;
    for (int o = w; o < 48; o += 16) {
        float s[K3ROWS];
#pragma unroll
        for (int r = 0; r < K3ROWS; r++) s[r] = 0.f;
        for (int k = lane; k < DINNER; k += 32) {
            float wv = Wx[o * DINNER + k];
#pragma unroll
            for (int r = 0; r < K3ROWS; r++) s[r] = fmaf(sx[r][k], wv, s[r]);
        }
#pragma unroll
        for (int off = 16; off; off >>= 1)
#pragma unroll
            for (int r = 0; r < K3ROWS; r++) s[r] += __shfl_down_sync(0xFFFFFFFFu, s[r], off);
        if (lane == 0) {
#pragma unroll
            for (int r = 0; r < K3ROWS; r++) sdbl[r][o] = s[r];
        }
    }
    __syncthreads();

    if (tid < K3ROWS * 16) {
        int r = tid >> 4, n = tid & 15;
        g_Bm[(size_t)(bl0 + r) * DSTATE + n] = sdbl[r][DTRANK + n];
    } else if (tid < 2 * K3ROWS * 16) {
        int t = tid - K3ROWS * 16;
        int r = t >> 4, n = t & 15;
        g_Cm[(size_t)(bl0 + r) * DSTATE + n] = sdbl[r][DTRANK + DSTATE + n];
    }

    float bv = bdt[tid];
    float wr[DTRANK];
#pragma unroll
    for (int i = 0; i < DTRANK; i++) wr[i] = Wdt[tid * DTRANK + i];
#pragma unroll
    for (int r = 0; r < K3ROWS; r++) {
        float acc = bv;
#pragma unroll
        for (int i = 0; i < DTRANK; i++) acc = fmaf(sdbl[r][i], wr[i], acc);
        float sp = fmaxf(acc, 0.f) + log1pf(expf(-fabsf(acc)));
        g_delta[(size_t)(bl0 + r) * DINNER + tid] = sp;
    }
}

// ---------------------------------------------------------------------------
// K4a: segmented selective scan, SPLIT-STATE version.
// Grid (64, 4, SEG), 256 threads = 128 channels x 2 halves.
// Thread t: dl = t>>1 (channel within tile), half = t&1 (states 8h..8h+7).
// Pair partners are adjacent lanes -> shfl_xor(1) merges the c scalar.
// ---------------------------------------------------------------------------
__device__ __forceinline__ void pow_tree8(float r, float* out) {
    // out[j] = r^(j+1), j = 0..7
    float r2 = r * r;
    float r4 = r2 * r2;
    out[0] = r;      out[1] = r2;      out[2] = r2 * r;  out[3] = r4;
    out[4] = r4 * r; out[5] = r4 * r2; out[6] = r4 * out[2]; out[7] = r4 * r4;
}

template <bool FAST>
__device__ __forceinline__ void seg_scan_half(
    int b, int d, int s, int half, const float* __restrict__ A,
    float Dp, const float* __restrict__ sB, const float* __restrict__ sC)
{
    float P[HSTATE], V[HSTATE], Wc[HSTATE];
#pragma unroll
    for (int j = 0; j < HSTATE; j++) { P[j] = 1.f; V[j] = 0.f; Wc[j] = 0.f; }
    float c = 0.f;
    const float A0 = A[0];           // global A[0] (channel's first state)
    const int n0 = half * HSTATE;

    const int l0 = s * LSEG;
    const float* pdelta = g_delta + ((size_t)(b * SEQLEN + l0)) * DINNER + d;
    const float* pxc    = g_xc    + ((size_t)(b * SEQLEN + l0)) * DINNER + d;
    const float* pz     = g_z     + ((size_t)(b * SEQLEN + l0)) * DINNER + d;

    float dt  = pdelta[0];
    float xcv = pxc[0];
    float zv  = pz[0];

#pragma unroll 4
    for (int l = 0; l < LSEG; l++) {
        float dtn = 0.f, xcn = 0.f, zvn = 0.f;
        if (l + 1 < LSEG) {
            dtn = pdelta[(l + 1) * DINNER];
            xcn = pxc[(l + 1) * DINNER];
            zvn = pz[(l + 1) * DINNER];
        }
        float gate = __fdividef(zv, 1.f + __expf(-zv));
        float du = dt * xcv;
        float yl = 0.f;

        float dA[HSTATE];
        if (FAST) {
            // dA[j] = r^(n0+j+1) = tree8(r)[j] * (half ? r^8 : 1)
            float r = __expf(dt * A0);
            pow_tree8(r, dA);
            if (half) {
                float r8 = dA[7];
#pragma unroll
                for (int j = 0; j < HSTATE; j++) dA[j] *= r8;
            }
        } else {
#pragma unroll
            for (int j = 0; j < HSTATE; j++) dA[j] = __expf(dt * A[n0 + j]);
        }

#pragma unroll
        for (int j = 0; j < HSTATE; j++) {
            float Bn = sB[l * DSTATE + n0 + j];
            float Cn = sC[l * DSTATE + n0 + j];
            P[j] *= dA[j];
            V[j] = fmaf(dA[j], V[j], du * Bn);
            yl = fmaf(V[j], Cn, yl);
            Wc[j] = fmaf(gate * Cn, P[j], Wc[j]);
        }
        // half 0 carries the D-skip term; y-dot parts summed across pair at end
        if (half == 0) yl = fmaf(xcv, Dp, yl);
        c = fmaf(gate, yl, c);
        dt = dtn; xcv = xcn; zv = zvn;
    }

    // merge c across the pair (partners are adjacent lanes)
    c += __shfl_xor_sync(0xFFFFFFFFu, c, 1);

    size_t base = (((size_t)s * BATCH + b) * DINNER + d) * DSTATE + n0;
#pragma unroll
    for (int q = 0; q < HSTATE; q += 4) {
        *reinterpret_cast<float4*>(&g_segP[base + q]) = make_float4(P[q], P[q+1], P[q+2], P[q+3]);
        *reinterpret_cast<float4*>(&g_segV[base + q]) = make_float4(V[q], V[q+1], V[q+2], V[q+3]);
        *reinterpret_cast<float4*>(&g_segW[base + q]) = make_float4(Wc[q], Wc[q+1], Wc[q+2], Wc[q+3]);
    }
    if (half == 0) g_segc[((size_t)s * BATCH + b) * DINNER + d] = c;
}

__global__ __launch_bounds__(256) void k4_seg(const float* __restrict__ A_log,
                                              const float* __restrict__ D_param) {
    const int b = blockIdx.x;
    const int tid = threadIdx.x;
    const int dl = tid >> 1;            // 0..127
    const int half = tid & 1;
    const int d = blockIdx.y * 128 + dl;
    const int s = blockIdx.z;

    __shared__ float sB[LSEG * DSTATE];
    __shared__ float sC[LSEG * DSTATE];
    {
        const float* gB = g_Bm + ((size_t)b * SEQLEN + s * LSEG) * DSTATE;
        const float* gC = g_Cm + ((size_t)b * SEQLEN + s * LSEG) * DSTATE;
        for (int i = tid * 4; i < LSEG * DSTATE; i += 256 * 4) {
            *reinterpret_cast<float4*>(&sB[i]) = *reinterpret_cast<const float4*>(&gB[i]);
            *reinterpret_cast<float4*>(&sC[i]) = *reinterpret_cast<const float4*>(&gC[i]);
        }
    }
    __syncthreads();

    float A[DSTATE];
    bool fast = true;
#pragma unroll
    for (int n = 0; n < DSTATE; n++) {
        A[n] = -expf(A_log[d * DSTATE + n]);
        fast = fast && (fabsf(A[n] - (float)(n + 1) * A[0]) <= 1e-4f * fabsf(A[n]));
    }
    const float Dp = D_param[d];

    if (fast) seg_scan_half<true >(b, d, s, half, A, Dp, sB, sC);
    else      seg_scan_half<false>(b, d, s, half, A, Dp, sB, sC);
}

// K4b: combine segments. Grid (64,4), 128 threads.
__global__ __launch_bounds__(128) void k4_combine() {
    const int b = blockIdx.x;
    const int d = blockIdx.y * 128 + threadIdx.x;

    float h[DSTATE];
#pragma unroll
    for (int n = 0; n < DSTATE; n++) h[n] = 0.f;
    float ysum = 0.f;

#pragma unroll
    for (int s = 0; s < SEG; s++) {
        size_t base = (((size_t)s * BATCH + b) * DINNER + d) * DSTATE;
        float dot = g_segc[((size_t)s * BATCH + b) * DINNER + d];
#pragma unroll
        for (int q = 0; q < DSTATE; q += 4) {
            float4 Wv = *reinterpret_cast<const float4*>(&g_segW[base + q]);
            float4 Pv = *reinterpret_cast<const float4*>(&g_segP[base + q]);
            float4 Vv = *reinterpret_cast<const float4*>(&g_segV[base + q]);
            dot = fmaf(Wv.x, h[q+0], dot);
            dot = fmaf(Wv.y, h[q+1], dot);
            dot = fmaf(Wv.z, h[q+2], dot);
            dot = fmaf(Wv.w, h[q+3], dot);
            h[q+0] = fmaf(Pv.x, h[q+0], Vv.x);
            h[q+1] = fmaf(Pv.y, h[q+1], Vv.y);
            h[q+2] = fmaf(Pv.z, h[q+2], Vv.z);
            h[q+3] = fmaf(Pv.w, h[q+3], Vv.w);
        }
        ysum += dot;
    }
    g_ybar[(size_t)b * DINNER + d] = ysum * (1.f / (float)SEQLEN);
}

// ---------------------------------------------------------------------------
// K5: head, warp-cooperative coalesced dots (R6-proven).
// ---------------------------------------------------------------------------
__device__ __forceinline__ float warp_dot(const float* __restrict__ wrow,
                                          const float* __restrict__ svec,
                                          int K, int lane) {
    float s = 0.f;
    for (int k = lane * 4; k < K; k += 128) {
        float4 wv = *reinterpret_cast<const float4*>(&wrow[k]);
        s = fmaf(svec[k + 0], wv.x, s);
        s = fmaf(svec[k + 1], wv.y, s);
        s = fmaf(svec[k + 2], wv.z, s);
        s = fmaf(svec[k + 3], wv.w, s);
    }
#pragma unroll
    for (int off = 16; off; off >>= 1) s += __shfl_down_sync(0xFFFFFFFFu, s, off);
    return s;
}

__global__ __launch_bounds__(256) void k5_head(const float* __restrict__ W_out,
                                               const float* __restrict__ W_outfc,
                                               const float* __restrict__ b_outfc,
                                               const float* __restrict__ W_mu,
                                               const float* __restrict__ b_mu,
                                               const float* __restrict__ W_sigma,
                                               const float* __restrict__ b_sigma,
                                               float* __restrict__ out) {
    const int b = blockIdx.x;
    const int tid = threadIdx.x;
    const int w = tid >> 5, lane = tid & 31;
    __shared__ float sy[DINNER];
    __shared__ float se[DMODEL];
    __shared__ float sxv[DIMIN];

    sy[tid] = g_ybar[(size_t)b * DINNER + tid];
    sy[tid + 256] = g_ybar[(size_t)b * DINNER + tid + 256];
    __syncthreads();

#pragma unroll
    for (int oi = 0; oi < 32; oi++) {
        const int o = w + oi * 8;
        float s = warp_dot(&W_out[o * DINNER], sy, DINNER, lane);
        if (lane == 0) se[o] = s;
    }
    __syncthreads();

#pragma unroll
    for (int oi = 0; oi < 32; oi++) {
        const int o = w + oi * 8;
        float s = warp_dot(&W_outfc[o * DMODEL], se, DMODEL, lane);
        if (lane == 0) {
            s += b_outfc[o];
            float t = tanhf(s);
            float xv = (t > 0.f) ? t : expm1f(t);
            sxv[o] = xv;
            out[(size_t)b * DIMIN + o] = xv;
        }
    }
    __syncthreads();

    float* out_mu    = out + BATCH * DIMIN;
    float* out_sigma = out + BATCH * DIMIN + BATCH * DIMOUT;
#pragma unroll
    for (int oi = 0; oi < 16; oi++) {
        const int o = w + oi * 8;
        if (o < DIMOUT) {
            float s = warp_dot(&W_mu[o * DIMIN], sxv, DIMIN, lane);
            if (lane == 0) out_mu[(size_t)b * DIMOUT + o] = s + b_mu[o];
        } else {
            const int o2 = o - DIMOUT;
            float s = warp_dot(&W_sigma[o2 * DIMIN], sxv, DIMIN, lane);
            if (lane == 0) {
                s += b_sigma[o2];
                float el = (s > 0.f) ? s : expm1f(s);
                out_sigma[(size_t)b * DIMOUT + o2] = el + 1.f + 1e-14f;
            }
        }
    }
}

// ---------------------------------------------------------------------------
extern "C" void kernel_launch(void* const* d_in, const int* in_sizes, int n_in,
                              void* d_out, int out_size) {
    const float* input   = (const float*)d_in[0];
    const float* W_in    = (const float*)d_in[1];
    const float* conv_w  = (const float*)d_in[2];
    const float* conv_b  = (const float*)d_in[3];
    const float* W_xproj = (const float*)d_in[4];
    const float* W_dt    = (const float*)d_in[5];
    const float* b_dt    = (const float*)d_in[6];
    const float* A_log   = (const float*)d_in[7];
    const float* D_param = (const float*)d_in[8];
    const float* W_out   = (const float*)d_in[9];
    const float* W_outfc = (const float*)d_in[10];
    const float* b_outfc = (const float*)d_in[11];
    const float* W_mu    = (const float*)d_in[12];
    const float* b_mu    = (const float*)d_in[13];
    const float* W_sigma = (const float*)d_in[14];
    const float* b_sigma = (const float*)d_in[15];
    float* out = (float*)d_out;

    k1_gemm<<<dim3(1024 / 128, BL / 128), 256>>>(input, W_in);
    k3_convproj<<<BL / K3ROWS, 512>>>(conv_w, conv_b, W_xproj, W_dt, b_dt);
    k4_seg<<<dim3(BATCH, DINNER / 128, SEG), 256>>>(A_log, D_param);
    k4_combine<<<dim3(BATCH, DINNER / 128), 128>>>();
    k5_head<<<BATCH, 256>>>(W_out, W_outfc, b_outfc, W_mu, b_mu, W_sigma, b_sigma, out);
}

// round 12
// speedup vs baseline: 1.0553x; 1.0553x over previous
#include <cuda_runtime.h>
#include <math.h>
#include <stdint.h>

// Problem dims
#define BATCH 64
#define SEQLEN 256
#define DMODEL 256
#define DINNER 512
#define DSTATE 16
#define DTRANK 16
#define DCONV 4
#define DIMIN 256
#define DIMOUT 64
#define BL (BATCH * SEQLEN)      // 16384
#define SEG 8
#define LSEG (SEQLEN / SEG)      // 32

// Scratch (device globals: no cudaMalloc allowed)
__device__ float g_xin[BL * DINNER];
__device__ float g_z[BL * DINNER];
__device__ float g_xc[BL * DINNER];
__device__ float g_delta[BL * DINNER];
__device__ float g_Bm[BL * DSTATE];
__device__ float g_Cm[BL * DSTATE];
__device__ float g_ybar[BATCH * DINNER];
// segment scan partials
__device__ float g_segW[SEG * BATCH * DINNER * DSTATE];
__device__ float g_segP[SEG * BATCH * DINNER * DSTATE];
__device__ float g_segV[SEG * BATCH * DINNER * DSTATE];
__device__ float g_segc[SEG * BATCH * DINNER];

// ---------------------------------------------------------------------------
// K1: xz = input @ W_in^T via tf32 tensor-core mma (R9-proven, verbatim).
// ---------------------------------------------------------------------------
__device__ __forceinline__ uint32_t f2tf32(float x) {
    uint32_t u;
    asm("cvt.rna.tf32.f32 %0, %1;" : "=r"(u) : "f"(x));
    return u;
}

__global__ __launch_bounds__(256) void k1_gemm(const float* __restrict__ X,
                                               const float* __restrict__ W) {
    __shared__ uint32_t Xs[128][36];
    __shared__ uint32_t Ws[128][36];

    const int m0 = blockIdx.y * 128;
    const int n0 = blockIdx.x * 128;
    const int tid = threadIdx.x;
    const int wid = tid >> 5;
    const int lane = tid & 31;
    const int warp_m = wid & 1;
    const int warp_n = wid >> 1;
    const int g = lane >> 2;
    const int tig = lane & 3;

    float c[4][4][4];
#pragma unroll
    for (int ma = 0; ma < 4; ma++)
#pragma unroll
        for (int na = 0; na < 4; na++)
#pragma unroll
            for (int q = 0; q < 4; q++) c[ma][na][q] = 0.f;

    const int lrow = tid >> 1;
    const int lc4 = (tid & 1) * 16;

#pragma unroll 1
    for (int chunk = 0; chunk < 8; chunk++) {
        const int k0 = chunk * 32;
#pragma unroll
        for (int i = 0; i < 4; i++) {
            float4 v = *reinterpret_cast<const float4*>(&X[(size_t)(m0 + lrow) * 256 + k0 + lc4 + i * 4]);
            Xs[lrow][lc4 + i * 4 + 0] = f2tf32(v.x);
            Xs[lrow][lc4 + i * 4 + 1] = f2tf32(v.y);
            Xs[lrow][lc4 + i * 4 + 2] = f2tf32(v.z);
            Xs[lrow][lc4 + i * 4 + 3] = f2tf32(v.w);
            float4 w = *reinterpret_cast<const float4*>(&W[(size_t)(n0 + lrow) * 256 + k0 + lc4 + i * 4]);
            Ws[lrow][lc4 + i * 4 + 0] = f2tf32(w.x);
            Ws[lrow][lc4 + i * 4 + 1] = f2tf32(w.y);
            Ws[lrow][lc4 + i * 4 + 2] = f2tf32(w.z);
            Ws[lrow][lc4 + i * 4 + 3] = f2tf32(w.w);
        }
        __syncthreads();

#pragma unroll
        for (int ks = 0; ks < 4; ks++) {
            const int kk = ks * 8;
            uint32_t a[4][4];
#pragma unroll
            for (int ma = 0; ma < 4; ma++) {
                const int ar = warp_m * 64 + ma * 16 + g;
                a[ma][0] = Xs[ar][kk + tig];
                a[ma][1] = Xs[ar + 8][kk + tig];
                a[ma][2] = Xs[ar][kk + tig + 4];
                a[ma][3] = Xs[ar + 8][kk + tig + 4];
            }
            uint32_t bfr[4][2];
#pragma unroll
            for (int na = 0; na < 4; na++) {
                const int br = warp_n * 32 + na * 8 + g;
                bfr[na][0] = Ws[br][kk + tig];
                bfr[na][1] = Ws[br][kk + tig + 4];
            }
#pragma unroll
            for (int ma = 0; ma < 4; ma++)
#pragma unroll
                for (int na = 0; na < 4; na++) {
                    asm volatile(
                        "mma.sync.aligned.m16n8k8.row.col.f32.tf32.tf32.f32 "
                        "{%0,%1,%2,%3}, {%4,%5,%6,%7}, {%8,%9}, {%0,%1,%2,%3};"
                        : "+f"(c[ma][na][0]), "+f"(c[ma][na][1]),
                          "+f"(c[ma][na][2]), "+f"(c[ma][na][3])
                        : "r"(a[ma][0]), "r"(a[ma][1]), "r"(a[ma][2]), "r"(a[ma][3]),
                          "r"(bfr[na][0]), "r"(bfr[na][1]));
                }
        }
        __syncthreads();
    }

    float* dstbase = (n0 < DINNER) ? g_xin : g_z;
    const int nbase = (n0 < DINNER) ? n0 : (n0 - DINNER);
#pragma unroll
    for (int ma = 0; ma < 4; ma++) {
        const int m = m0 + warp_m * 64 + ma * 16 + g;
#pragma unroll
        for (int na = 0; na < 4; na++) {
            const int n = nbase + warp_n * 32 + na * 8 + tig * 2;
            *reinterpret_cast<float2*>(&dstbase[(size_t)m * DINNER + n]) =
                make_float2(c[ma][na][0], c[ma][na][1]);
            *reinterpret_cast<float2*>(&dstbase[(size_t)(m + 8) * DINNER + n]) =
                make_float2(c[ma][na][2], c[ma][na][3]);
        }
    }
}

// ---------------------------------------------------------------------------
// K3 (fused conv + 8-row proj), smem-bytes-reduced inner loop:
// each warp's 3 outputs share one sx read (3x fewer LDS bytes), float4 loads.
// ---------------------------------------------------------------------------
#define K3ROWS 8
__global__ __launch_bounds__(512) void k3_convproj(const float* __restrict__ cw,
                                                   const float* __restrict__ cb,
                                                   const float* __restrict__ Wx,
                                                   const float* __restrict__ Wdt,
                                                   const float* __restrict__ bdt) {
    const int bl0 = blockIdx.x * K3ROWS;
    const int l0 = bl0 & (SEQLEN - 1);
    __shared__ float sx[K3ROWS + 3][DINNER];
    __shared__ float sdbl[K3ROWS][48];
    const int tid = threadIdx.x;

#pragma unroll
    for (int j = 0; j < K3ROWS + 3; j++) {
        int bl = bl0 - 3 + j;
        sx[j][tid] = (l0 + j >= 3) ? g_xin[(size_t)bl * DINNER + tid] : 0.f;
    }

    const float w0c = cw[tid * 4 + 0], w1c = cw[tid * 4 + 1];
    const float w2c = cw[tid * 4 + 2], w3c = cw[tid * 4 + 3];
    const float bias = cb[tid];
#pragma unroll
    for (int r = 0; r < K3ROWS; r++) {
        float sum = bias;
        sum = fmaf(sx[r + 0][tid], w0c, sum);
        sum = fmaf(sx[r + 1][tid], w1c, sum);
        sum = fmaf(sx[r + 2][tid], w2c, sum);
        sum = fmaf(sx[r + 3][tid], w3c, sum);
        float xc = sum / (1.f + expf(-sum));
        sx[r][tid] = xc;
        g_xc[(size_t)(bl0 + r) * DINNER + tid] = xc;
    }
    __syncthreads();

    const int w = tid >> 5, lane = tid & 31;
    const int o0 = w, o1 = w + 16, o2 = w + 32;   // covers 0..47
    {
        float s0[K3ROWS], s1[K3ROWS], s2[K3ROWS];
#pragma unroll
        for (int r = 0; r < K3ROWS; r++) { s0[r] = 0.f; s1[r] = 0.f; s2[r] = 0.f; }

#pragma unroll
        for (int it = 0; it < DINNER / 128; it++) {
            const int k = it * 128 + lane * 4;
            float4 wv0 = *reinterpret_cast<const float4*>(&Wx[o0 * DINNER + k]);
            float4 wv1 = *reinterpret_cast<const float4*>(&Wx[o1 * DINNER + k]);
            float4 wv2 = *reinterpret_cast<const float4*>(&Wx[o2 * DINNER + k]);
#pragma unroll
            for (int r = 0; r < K3ROWS; r++) {
                float4 xv = *reinterpret_cast<const float4*>(&sx[r][k]);
                s0[r] = fmaf(xv.x, wv0.x, s0[r]); s0[r] = fmaf(xv.y, wv0.y, s0[r]);
                s0[r] = fmaf(xv.z, wv0.z, s0[r]); s0[r] = fmaf(xv.w, wv0.w, s0[r]);
                s1[r] = fmaf(xv.x, wv1.x, s1[r]); s1[r] = fmaf(xv.y, wv1.y, s1[r]);
                s1[r] = fmaf(xv.z, wv1.z, s1[r]); s1[r] = fmaf(xv.w, wv1.w, s1[r]);
                s2[r] = fmaf(xv.x, wv2.x, s2[r]); s2[r] = fmaf(xv.y, wv2.y, s2[r]);
                s2[r] = fmaf(xv.z, wv2.z, s2[r]); s2[r] = fmaf(xv.w, wv2.w, s2[r]);
            }
        }
#pragma unroll
        for (int off = 16; off; off >>= 1) {
#pragma unroll
            for (int r = 0; r < K3ROWS; r++) {
                s0[r] += __shfl_down_sync(0xFFFFFFFFu, s0[r], off);
                s1[r] += __shfl_down_sync(0xFFFFFFFFu, s1[r], off);
                s2[r] += __shfl_down_sync(0xFFFFFFFFu, s2[r], off);
            }
        }
        if (lane == 0) {
#pragma unroll
            for (int r = 0; r < K3ROWS; r++) {
                sdbl[r][o0] = s0[r];
                sdbl[r][o1] = s1[r];
                sdbl[r][o2] = s2[r];
            }
        }
    }
    __syncthreads();

    if (tid < K3ROWS * 16) {
        int r = tid >> 4, n = tid & 15;
        g_Bm[(size_t)(bl0 + r) * DSTATE + n] = sdbl[r][DTRANK + n];
    } else if (tid < 2 * K3ROWS * 16) {
        int t = tid - K3ROWS * 16;
        int r = t >> 4, n = t & 15;
        g_Cm[(size_t)(bl0 + r) * DSTATE + n] = sdbl[r][DTRANK + DSTATE + n];
    }

    float bv = bdt[tid];
    float wr[DTRANK];
#pragma unroll
    for (int i = 0; i < DTRANK; i++) wr[i] = Wdt[tid * DTRANK + i];
#pragma unroll
    for (int r = 0; r < K3ROWS; r++) {
        float acc = bv;
#pragma unroll
        for (int i = 0; i < DTRANK; i++) acc = fmaf(sdbl[r][i], wr[i], acc);
        float sp = fmaxf(acc, 0.f) + log1pf(expf(-fabsf(acc)));
        g_delta[(size_t)(bl0 + r) * DINNER + tid] = sp;
    }
}

// ---------------------------------------------------------------------------
// K4a: segmented selective scan (R9-proven, verbatim). Grid (64,4,SEG), 128 thr.
// ---------------------------------------------------------------------------
__device__ __forceinline__ void pow_tree(float r, float* out) {
    float r2 = r * r;
    float r4 = r2 * r2;
    float r8 = r4 * r4;
    out[0]  = r;          out[1]  = r2;         out[2]  = r2 * r;      out[3]  = r4;
    out[4]  = r4 * r;     out[5]  = r4 * r2;    out[6]  = r4 * out[2]; out[7]  = r8;
    out[8]  = r8 * r;     out[9]  = r8 * r2;    out[10] = r8 * out[2]; out[11] = r8 * r4;
    out[12] = r8 * out[4]; out[13] = r8 * out[5]; out[14] = r8 * out[6]; out[15] = r8 * r8;
}

template <bool FAST>
__device__ __forceinline__ void seg_scan_body(
    int b, int d, int s, const float* __restrict__ A,
    float Dp, const float* __restrict__ sB, const float* __restrict__ sC)
{
    float V[DSTATE], Wc[DSTATE];
#pragma unroll
    for (int n = 0; n < DSTATE; n++) { V[n] = 0.f; Wc[n] = 0.f; }
    float Pfull[DSTATE];
    if (!FAST) {
#pragma unroll
        for (int n = 0; n < DSTATE; n++) Pfull[n] = 1.f;
    }
    float Rcum = 1.f;
    float c = 0.f;
    const float A0 = A[0];

    const int l0 = s * LSEG;
    const float* pdelta = g_delta + ((size_t)(b * SEQLEN + l0)) * DINNER + d;
    const float* pxc    = g_xc    + ((size_t)(b * SEQLEN + l0)) * DINNER + d;
    const float* pz     = g_z     + ((size_t)(b * SEQLEN + l0)) * DINNER + d;

    float dt  = pdelta[0];
    float xcv = pxc[0];
    float zv  = pz[0];

#pragma unroll 4
    for (int l = 0; l < LSEG; l++) {
        float dtn = 0.f, xcn = 0.f, zvn = 0.f;
        if (l + 1 < LSEG) {
            dtn = pdelta[(l + 1) * DINNER];
            xcn = pxc[(l + 1) * DINNER];
            zvn = pz[(l + 1) * DINNER];
        }
        float gate = __fdividef(zv, 1.f + __expf(-zv));
        float du = dt * xcv;
        float yl = 0.f;

        float dA[DSTATE];
        float Pw[DSTATE];
        if (FAST) {
            float r = __expf(dt * A0);
            pow_tree(r, dA);
            Rcum *= r;
            pow_tree(Rcum, Pw);
        } else {
#pragma unroll
            for (int n = 0; n < DSTATE; n++) {
                dA[n] = __expf(dt * A[n]);
                Pfull[n] *= dA[n];
                Pw[n] = Pfull[n];
            }
        }

#pragma unroll
        for (int n = 0; n < DSTATE; n++) {
            float Bn = sB[l * DSTATE + n];
            float Cn = sC[l * DSTATE + n];
            V[n] = fmaf(dA[n], V[n], du * Bn);
            yl = fmaf(V[n], Cn, yl);
            Wc[n] = fmaf(gate * Cn, Pw[n], Wc[n]);
        }
        c = fmaf(gate, fmaf(xcv, Dp, yl), c);
        dt = dtn; xcv = xcn; zv = zvn;
    }

    float Pout[DSTATE];
    if (FAST) pow_tree(Rcum, Pout);
    else {
#pragma unroll
        for (int n = 0; n < DSTATE; n++) Pout[n] = Pfull[n];
    }

    size_t base = (((size_t)s * BATCH + b) * DINNER + d) * DSTATE;
#pragma unroll
    for (int q = 0; q < DSTATE; q += 4) {
        *reinterpret_cast<float4*>(&g_segP[base + q]) = make_float4(Pout[q], Pout[q+1], Pout[q+2], Pout[q+3]);
        *reinterpret_cast<float4*>(&g_segV[base + q]) = make_float4(V[q], V[q+1], V[q+2], V[q+3]);
        *reinterpret_cast<float4*>(&g_segW[base + q]) = make_float4(Wc[q], Wc[q+1], Wc[q+2], Wc[q+3]);
    }
    g_segc[((size_t)s * BATCH + b) * DINNER + d] = c;
}

__global__ __launch_bounds__(128) void k4_seg(const float* __restrict__ A_log,
                                              const float* __restrict__ D_param) {
    const int b = blockIdx.x;
    const int d = blockIdx.y * 128 + threadIdx.x;
    const int s = blockIdx.z;

    __shared__ float sB[LSEG * DSTATE];
    __shared__ float sC[LSEG * DSTATE];
    {
        const float* gB = g_Bm + ((size_t)b * SEQLEN + s * LSEG) * DSTATE;
        const float* gC = g_Cm + ((size_t)b * SEQLEN + s * LSEG) * DSTATE;
        for (int i = threadIdx.x * 4; i < LSEG * DSTATE; i += 128 * 4) {
            *reinterpret_cast<float4*>(&sB[i]) = *reinterpret_cast<const float4*>(&gB[i]);
            *reinterpret_cast<float4*>(&sC[i]) = *reinterpret_cast<const float4*>(&gC[i]);
        }
    }
    __syncthreads();

    float A[DSTATE];
    bool fast = true;
#pragma unroll
    for (int n = 0; n < DSTATE; n++) {
        A[n] = -expf(A_log[d * DSTATE + n]);
        fast = fast && (fabsf(A[n] - (float)(n + 1) * A[0]) <= 1e-4f * fabsf(A[n]));
    }
    const float Dp = D_param[d];

    if (fast) seg_scan_body<true >(b, d, s, A, Dp, sB, sC);
    else      seg_scan_body<false>(b, d, s, A, Dp, sB, sC);
}

// K4b: combine segments. Grid (64,4), 128 threads.
__global__ __launch_bounds__(128) void k4_combine() {
    const int b = blockIdx.x;
    const int d = blockIdx.y * 128 + threadIdx.x;

    float h[DSTATE];
#pragma unroll
    for (int n = 0; n < DSTATE; n++) h[n] = 0.f;
    float ysum = 0.f;

#pragma unroll
    for (int s = 0; s < SEG; s++) {
        size_t base = (((size_t)s * BATCH + b) * DINNER + d) * DSTATE;
        float dot = g_segc[((size_t)s * BATCH + b) * DINNER + d];
#pragma unroll
        for (int q = 0; q < DSTATE; q += 4) {
            float4 Wv = *reinterpret_cast<const float4*>(&g_segW[base + q]);
            float4 Pv = *reinterpret_cast<const float4*>(&g_segP[base + q]);
            float4 Vv = *reinterpret_cast<const float4*>(&g_segV[base + q]);
            dot = fmaf(Wv.x, h[q+0], dot);
            dot = fmaf(Wv.y, h[q+1], dot);
            dot = fmaf(Wv.z, h[q+2], dot);
            dot = fmaf(Wv.w, h[q+3], dot);
            h[q+0] = fmaf(Pv.x, h[q+0], Vv.x);
            h[q+1] = fmaf(Pv.y, h[q+1], Vv.y);
            h[q+2] = fmaf(Pv.z, h[q+2], Vv.z);
            h[q+3] = fmaf(Pv.w, h[q+3], Vv.w);
        }
        ysum += dot;
    }
    g_ybar[(size_t)b * DINNER + d] = ysum * (1.f / (float)SEQLEN);
}

// ---------------------------------------------------------------------------
// K5: head, warp-cooperative coalesced dots (R6-proven).
// ---------------------------------------------------------------------------
__device__ __forceinline__ float warp_dot(const float* __restrict__ wrow,
                                          const float* __restrict__ svec,
                                          int K, int lane) {
    float s = 0.f;
    for (int k = lane * 4; k < K; k += 128) {
        float4 wv = *reinterpret_cast<const float4*>(&wrow[k]);
        s = fmaf(svec[k + 0], wv.x, s);
        s = fmaf(svec[k + 1], wv.y, s);
        s = fmaf(svec[k + 2], wv.z, s);
        s = fmaf(svec[k + 3], wv.w, s);
    }
#pragma unroll
    for (int off = 16; off; off >>= 1) s += __shfl_down_sync(0xFFFFFFFFu, s, off);
    return s;
}

__global__ __launch_bounds__(256) void k5_head(const float* __restrict__ W_out,
                                               const float* __restrict__ W_outfc,
                                               const float* __restrict__ b_outfc,
                                               const float* __restrict__ W_mu,
                                               const float* __restrict__ b_mu,
                                               const float* __restrict__ W_sigma,
                                               const float* __restrict__ b_sigma,
                                               float* __restrict__ out) {
    const int b = blockIdx.x;
    const int tid = threadIdx.x;
    const int w = tid >> 5, lane = tid & 31;
    __shared__ float sy[DINNER];
    __shared__ float se[DMODEL];
    __shared__ float sxv[DIMIN];

    sy[tid] = g_ybar[(size_t)b * DINNER + tid];
    sy[tid + 256] = g_ybar[(size_t)b * DINNER + tid + 256];
    __syncthreads();

#pragma unroll
    for (int oi = 0; oi < 32; oi++) {
        const int o = w + oi * 8;
        float s = warp_dot(&W_out[o * DINNER], sy, DINNER, lane);
        if (lane == 0) se[o] = s;
    }
    __syncthreads();

#pragma unroll
    for (int oi = 0; oi < 32; oi++) {
        const int o = w + oi * 8;
        float s = warp_dot(&W_outfc[o * DMODEL], se, DMODEL, lane);
        if (lane == 0) {
            s += b_outfc[o];
            float t = tanhf(s);
            float xv = (t > 0.f) ? t : expm1f(t);
            sxv[o] = xv;
            out[(size_t)b * DIMIN + o] = xv;
        }
    }
    __syncthreads();

    float* out_mu    = out + BATCH * DIMIN;
    float* out_sigma = out + BATCH * DIMIN + BATCH * DIMOUT;
#pragma unroll
    for (int oi = 0; oi < 16; oi++) {
        const int o = w + oi * 8;
        if (o < DIMOUT) {
            float s = warp_dot(&W_mu[o * DIMIN], sxv, DIMIN, lane);
            if (lane == 0) out_mu[(size_t)b * DIMOUT + o] = s + b_mu[o];
        } else {
            const int o2 = o - DIMOUT;
            float s = warp_dot(&W_sigma[o2 * DIMIN], sxv, DIMIN, lane);
            if (lane == 0) {
                s += b_sigma[o2];
                float el = (s > 0.f) ? s : expm1f(s);
                out_sigma[(size_t)b * DIMOUT + o2] = el + 1.f + 1e-14f;
            }
        }
    }
}

// ---------------------------------------------------------------------------
extern "C" void kernel_launch(void* const* d_in, const int* in_sizes, int n_in,
                              void* d_out, int out_size) {
    const float* input   = (const float*)d_in[0];
    const float* W_in    = (const float*)d_in[1];
    const float* conv_w  = (const float*)d_in[2];
    const float* conv_b  = (const float*)d_in[3];
    const float* W_xproj = (const float*)d_in[4];
    const float* W_dt    = (const float*)d_in[5];
    const float* b_dt    = (const float*)d_in[6];
    const float* A_log   = (const float*)d_in[7];
    const float* D_param = (const float*)d_in[8];
    const float* W_out   = (const float*)d_in[9];
    const float* W_outfc = (const float*)d_in[10];
    const float* b_outfc = (const float*)d_in[11];
    const float* W_mu    = (const float*)d_in[12];
    const float* b_mu    = (const float*)d_in[13];
    const float* W_sigma = (const float*)d_in[14];
    const float* b_sigma = (const float*)d_in[15];
    float* out = (float*)d_out;

    k1_gemm<<<dim3(1024 / 128, BL / 128), 256>>>(input, W_in);
    k3_convproj<<<BL / K3ROWS, 512>>>(conv_w, conv_b, W_xproj, W_dt, b_dt);
    k4_seg<<<dim3(BATCH, DINNER / 128, SEG), 128>>>(A_log, D_param);
    k4_combine<<<dim3(BATCH, DINNER / 128), 128>>>();
    k5_head<<<BATCH, 256>>>(W_out, W_outfc, b_outfc, W_mu, b_mu, W_sigma, b_sigma, out);
}

// round 14
// speedup vs baseline: 1.0994x; 1.0418x over previous
#include <cuda_runtime.h>
#include <math.h>
#include <stdint.h>

// Problem dims
#define BATCH 64
#define SEQLEN 256
#define DMODEL 256
#define DINNER 512
#define DSTATE 16
#define DTRANK 16
#define DCONV 4
#define DIMIN 256
#define DIMOUT 64
#define BL (BATCH * SEQLEN)      // 16384
#define SEG 8
#define LSEG (SEQLEN / SEG)      // 32

// Scratch (device globals: no cudaMalloc allowed)
__device__ float g_xin[BL * DINNER];
__device__ float g_z[BL * DINNER];
__device__ float g_xc[BL * DINNER];
__device__ float g_delta[BL * DINNER];
__device__ float g_Bm[BL * DSTATE];
__device__ float g_Cm[BL * DSTATE];
__device__ float g_ybar[BATCH * DINNER];
// segment scan partials
__device__ float g_segW[SEG * BATCH * DINNER * DSTATE];
__device__ float g_segP[SEG * BATCH * DINNER * DSTATE];
__device__ float g_segV[SEG * BATCH * DINNER * DSTATE];
__device__ float g_segc[SEG * BATCH * DINNER];

// ---------------------------------------------------------------------------
// K1: xz = input @ W_in^T via tf32 mma, 512 threads / 16 warps, warp tile
// 32x32 (2x4 m16n8 atoms). Block tile 128x128, K chunked by 32.
// More warps/SMSP (4 vs 2) to hide LDS->mma dependency stalls.
// ---------------------------------------------------------------------------
__device__ __forceinline__ uint32_t f2tf32(float x) {
    uint32_t u;
    asm("cvt.rna.tf32.f32 %0, %1;" : "=r"(u) : "f"(x));
    return u;
}

__global__ __launch_bounds__(512) void k1_gemm(const float* __restrict__ X,
                                               const float* __restrict__ W) {
    __shared__ uint32_t Xs[128][36];   // [m][k], stride 36 -> bank 4g+tig, conflict-free
    __shared__ uint32_t Ws[128][36];   // [n][k]

    const int m0 = blockIdx.y * 128;
    const int n0 = blockIdx.x * 128;
    const int tid = threadIdx.x;
    const int wid = tid >> 5;
    const int lane = tid & 31;
    const int warp_m = wid & 3;        // 4 warps in m (32 rows each)
    const int warp_n = wid >> 2;       // 4 warps in n (32 cols each)
    const int g = lane >> 2;           // 0..7
    const int tig = lane & 3;          // 0..3

    float c[2][4][4];
#pragma unroll
    for (int ma = 0; ma < 2; ma++)
#pragma unroll
        for (int na = 0; na < 4; na++)
#pragma unroll
            for (int q = 0; q < 4; q++) c[ma][na][q] = 0.f;

    const int lrow = tid >> 2;         // 0..127
    const int lc = (tid & 3) * 8;      // 0,8,16,24

#pragma unroll 1
    for (int chunk = 0; chunk < 8; chunk++) {
        const int k0 = chunk * 32;
#pragma unroll
        for (int i = 0; i < 2; i++) {
            float4 v = *reinterpret_cast<const float4*>(&X[(size_t)(m0 + lrow) * 256 + k0 + lc + i * 4]);
            Xs[lrow][lc + i * 4 + 0] = f2tf32(v.x);
            Xs[lrow][lc + i * 4 + 1] = f2tf32(v.y);
            Xs[lrow][lc + i * 4 + 2] = f2tf32(v.z);
            Xs[lrow][lc + i * 4 + 3] = f2tf32(v.w);
            float4 w = *reinterpret_cast<const float4*>(&W[(size_t)(n0 + lrow) * 256 + k0 + lc + i * 4]);
            Ws[lrow][lc + i * 4 + 0] = f2tf32(w.x);
            Ws[lrow][lc + i * 4 + 1] = f2tf32(w.y);
            Ws[lrow][lc + i * 4 + 2] = f2tf32(w.z);
            Ws[lrow][lc + i * 4 + 3] = f2tf32(w.w);
        }
        __syncthreads();

#pragma unroll
        for (int ks = 0; ks < 4; ks++) {
            const int kk = ks * 8;
            uint32_t a[2][4];
#pragma unroll
            for (int ma = 0; ma < 2; ma++) {
                const int ar = warp_m * 32 + ma * 16 + g;
                a[ma][0] = Xs[ar][kk + tig];
                a[ma][1] = Xs[ar + 8][kk + tig];
                a[ma][2] = Xs[ar][kk + tig + 4];
                a[ma][3] = Xs[ar + 8][kk + tig + 4];
            }
            uint32_t bfr[4][2];
#pragma unroll
            for (int na = 0; na < 4; na++) {
                const int br = warp_n * 32 + na * 8 + g;
                bfr[na][0] = Ws[br][kk + tig];
                bfr[na][1] = Ws[br][kk + tig + 4];
            }
#pragma unroll
            for (int ma = 0; ma < 2; ma++)
#pragma unroll
                for (int na = 0; na < 4; na++) {
                    asm volatile(
                        "mma.sync.aligned.m16n8k8.row.col.f32.tf32.tf32.f32 "
                        "{%0,%1,%2,%3}, {%4,%5,%6,%7}, {%8,%9}, {%0,%1,%2,%3};"
                        : "+f"(c[ma][na][0]), "+f"(c[ma][na][1]),
                          "+f"(c[ma][na][2]), "+f"(c[ma][na][3])
                        : "r"(a[ma][0]), "r"(a[ma][1]), "r"(a[ma][2]), "r"(a[ma][3]),
                          "r"(bfr[na][0]), "r"(bfr[na][1]));
                }
        }
        __syncthreads();
    }

    float* dstbase = (n0 < DINNER) ? g_xin : g_z;
    const int nbase = (n0 < DINNER) ? n0 : (n0 - DINNER);
#pragma unroll
    for (int ma = 0; ma < 2; ma++) {
        const int m = m0 + warp_m * 32 + ma * 16 + g;
#pragma unroll
        for (int na = 0; na < 4; na++) {
            const int n = nbase + warp_n * 32 + na * 8 + tig * 2;
            *reinterpret_cast<float2*>(&dstbase[(size_t)m * DINNER + n]) =
                make_float2(c[ma][na][0], c[ma][na][1]);
            *reinterpret_cast<float2*>(&dstbase[(size_t)(m + 8) * DINNER + n]) =
                make_float2(c[ma][na][2], c[ma][na][3]);
        }
    }
}

// ---------------------------------------------------------------------------
// K3 (fused conv + 8-row proj), smem-bytes-reduced inner loop (R12-proven).
// ---------------------------------------------------------------------------
#define K3ROWS 8
__global__ __launch_bounds__(512) void k3_convproj(const float* __restrict__ cw,
                                                   const float* __restrict__ cb,
                                                   const float* __restrict__ Wx,
                                                   const float* __restrict__ Wdt,
                                                   const float* __restrict__ bdt) {
    const int bl0 = blockIdx.x * K3ROWS;
    const int l0 = bl0 & (SEQLEN - 1);
    __shared__ float sx[K3ROWS + 3][DINNER];
    __shared__ float sdbl[K3ROWS][48];
    const int tid = threadIdx.x;

#pragma unroll
    for (int j = 0; j < K3ROWS + 3; j++) {
        int bl = bl0 - 3 + j;
        sx[j][tid] = (l0 + j >= 3) ? g_xin[(size_t)bl * DINNER + tid] : 0.f;
    }

    const float w0c = cw[tid * 4 + 0], w1c = cw[tid * 4 + 1];
    const float w2c = cw[tid * 4 + 2], w3c = cw[tid * 4 + 3];
    const float bias = cb[tid];
#pragma unroll
    for (int r = 0; r < K3ROWS; r++) {
        float sum = bias;
        sum = fmaf(sx[r + 0][tid], w0c, sum);
        sum = fmaf(sx[r + 1][tid], w1c, sum);
        sum = fmaf(sx[r + 2][tid], w2c, sum);
        sum = fmaf(sx[r + 3][tid], w3c, sum);
        float xc = sum / (1.f + expf(-sum));
        sx[r][tid] = xc;
        g_xc[(size_t)(bl0 + r) * DINNER + tid] = xc;
    }
    __syncthreads();

    const int w = tid >> 5, lane = tid & 31;
    const int o0 = w, o1 = w + 16, o2 = w + 32;
    {
        float s0[K3ROWS], s1[K3ROWS], s2[K3ROWS];
#pragma unroll
        for (int r = 0; r < K3ROWS; r++) { s0[r] = 0.f; s1[r] = 0.f; s2[r] = 0.f; }

#pragma unroll
        for (int it = 0; it < DINNER / 128; it++) {
            const int k = it * 128 + lane * 4;
            float4 wv0 = *reinterpret_cast<const float4*>(&Wx[o0 * DINNER + k]);
            float4 wv1 = *reinterpret_cast<const float4*>(&Wx[o1 * DINNER + k]);
            float4 wv2 = *reinterpret_cast<const float4*>(&Wx[o2 * DINNER + k]);
#pragma unroll
            for (int r = 0; r < K3ROWS; r++) {
                float4 xv = *reinterpret_cast<const float4*>(&sx[r][k]);
                s0[r] = fmaf(xv.x, wv0.x, s0[r]); s0[r] = fmaf(xv.y, wv0.y, s0[r]);
                s0[r] = fmaf(xv.z, wv0.z, s0[r]); s0[r] = fmaf(xv.w, wv0.w, s0[r]);
                s1[r] = fmaf(xv.x, wv1.x, s1[r]); s1[r] = fmaf(xv.y, wv1.y, s1[r]);
                s1[r] = fmaf(xv.z, wv1.z, s1[r]); s1[r] = fmaf(xv.w, wv1.w, s1[r]);
                s2[r] = fmaf(xv.x, wv2.x, s2[r]); s2[r] = fmaf(xv.y, wv2.y, s2[r]);
                s2[r] = fmaf(xv.z, wv2.z, s2[r]); s2[r] = fmaf(xv.w, wv2.w, s2[r]);
            }
        }
#pragma unroll
        for (int off = 16; off; off >>= 1) {
#pragma unroll
            for (int r = 0; r < K3ROWS; r++) {
                s0[r] += __shfl_down_sync(0xFFFFFFFFu, s0[r], off);
                s1[r] += __shfl_down_sync(0xFFFFFFFFu, s1[r], off);
                s2[r] += __shfl_down_sync(0xFFFFFFFFu, s2[r], off);
            }
        }
        if (lane == 0) {
#pragma unroll
            for (int r = 0; r < K3ROWS; r++) {
                sdbl[r][o0] = s0[r];
                sdbl[r][o1] = s1[r];
                sdbl[r][o2] = s2[r];
            }
        }
    }
    __syncthreads();

    if (tid < K3ROWS * 16) {
        int r = tid >> 4, n = tid & 15;
        g_Bm[(size_t)(bl0 + r) * DSTATE + n] = sdbl[r][DTRANK + n];
    } else if (tid < 2 * K3ROWS * 16) {
        int t = tid - K3ROWS * 16;
        int r = t >> 4, n = t & 15;
        g_Cm[(size_t)(bl0 + r) * DSTATE + n] = sdbl[r][DTRANK + DSTATE + n];
    }

    float bv = bdt[tid];
    float wr[DTRANK];
#pragma unroll
    for (int i = 0; i < DTRANK; i++) wr[i] = Wdt[tid * DTRANK + i];
#pragma unroll
    for (int r = 0; r < K3ROWS; r++) {
        float acc = bv;
#pragma unroll
        for (int i = 0; i < DTRANK; i++) acc = fmaf(sdbl[r][i], wr[i], acc);
        float sp = fmaxf(acc, 0.f) + log1pf(expf(-fabsf(acc)));
        g_delta[(size_t)(bl0 + r) * DINNER + tid] = sp;
    }
}

// ---------------------------------------------------------------------------
// K4a: segmented selective scan (R9-proven, verbatim). Grid (64,4,SEG), 128 thr.
// ---------------------------------------------------------------------------
__device__ __forceinline__ void pow_tree(float r, float* out) {
    float r2 = r * r;
    float r4 = r2 * r2;
    float r8 = r4 * r4;
    out[0]  = r;          out[1]  = r2;         out[2]  = r2 * r;      out[3]  = r4;
    out[4]  = r4 * r;     out[5]  = r4 * r2;    out[6]  = r4 * out[2]; out[7]  = r8;
    out[8]  = r8 * r;     out[9]  = r8 * r2;    out[10] = r8 * out[2]; out[11] = r8 * r4;
    out[12] = r8 * out[4]; out[13] = r8 * out[5]; out[14] = r8 * out[6]; out[15] = r8 * r8;
}

template <bool FAST>
__device__ __forceinline__ void seg_scan_body(
    int b, int d, int s, const float* __restrict__ A,
    float Dp, const float* __restrict__ sB, const float* __restrict__ sC)
{
    float V[DSTATE], Wc[DSTATE];
#pragma unroll
    for (int n = 0; n < DSTATE; n++) { V[n] = 0.f; Wc[n] = 0.f; }
    float Pfull[DSTATE];
    if (!FAST) {
#pragma unroll
        for (int n = 0; n < DSTATE; n++) Pfull[n] = 1.f;
    }
    float Rcum = 1.f;
    float c = 0.f;
    const float A0 = A[0];

    const int l0 = s * LSEG;
    const float* pdelta = g_delta + ((size_t)(b * SEQLEN + l0)) * DINNER + d;
    const float* pxc    = g_xc    + ((size_t)(b * SEQLEN + l0)) * DINNER + d;
    const float* pz     = g_z     + ((size_t)(b * SEQLEN + l0)) * DINNER + d;

    float dt  = pdelta[0];
    float xcv = pxc[0];
    float zv  = pz[0];

#pragma unroll 4
    for (int l = 0; l < LSEG; l++) {
        float dtn = 0.f, xcn = 0.f, zvn = 0.f;
        if (l + 1 < LSEG) {
            dtn = pdelta[(l + 1) * DINNER];
            xcn = pxc[(l + 1) * DINNER];
            zvn = pz[(l + 1) * DINNER];
        }
        float gate = __fdividef(zv, 1.f + __expf(-zv));
        float du = dt * xcv;
        float yl = 0.f;

        float dA[DSTATE];
        float Pw[DSTATE];
        if (FAST) {
            float r = __expf(dt * A0);
            pow_tree(r, dA);
            Rcum *= r;
            pow_tree(Rcum, Pw);
        } else {
#pragma unroll
            for (int n = 0; n < DSTATE; n++) {
                dA[n] = __expf(dt * A[n]);
                Pfull[n] *= dA[n];
                Pw[n] = Pfull[n];
            }
        }

#pragma unroll
        for (int n = 0; n < DSTATE; n++) {
            float Bn = sB[l * DSTATE + n];
            float Cn = sC[l * DSTATE + n];
            V[n] = fmaf(dA[n], V[n], du * Bn);
            yl = fmaf(V[n], Cn, yl);
            Wc[n] = fmaf(gate * Cn, Pw[n], Wc[n]);
        }
        c = fmaf(gate, fmaf(xcv, Dp, yl), c);
        dt = dtn; xcv = xcn; zv = zvn;
    }

    float Pout[DSTATE];
    if (FAST) pow_tree(Rcum, Pout);
    else {
#pragma unroll
        for (int n = 0; n < DSTATE; n++) Pout[n] = Pfull[n];
    }

    size_t base = (((size_t)s * BATCH + b) * DINNER + d) * DSTATE;
#pragma unroll
    for (int q = 0; q < DSTATE; q += 4) {
        *reinterpret_cast<float4*>(&g_segP[base + q]) = make_float4(Pout[q], Pout[q+1], Pout[q+2], Pout[q+3]);
        *reinterpret_cast<float4*>(&g_segV[base + q]) = make_float4(V[q], V[q+1], V[q+2], V[q+3]);
        *reinterpret_cast<float4*>(&g_segW[base + q]) = make_float4(Wc[q], Wc[q+1], Wc[q+2], Wc[q+3]);
    }
    g_segc[((size_t)s * BATCH + b) * DINNER + d] = c;
}

__global__ __launch_bounds__(128) void k4_seg(const float* __restrict__ A_log,
                                              const float* __restrict__ D_param) {
    const int b = blockIdx.x;
    const int d = blockIdx.y * 128 + threadIdx.x;
    const int s = blockIdx.z;

    __shared__ float sB[LSEG * DSTATE];
    __shared__ float sC[LSEG * DSTATE];
    {
        const float* gB = g_Bm + ((size_t)b * SEQLEN + s * LSEG) * DSTATE;
        const float* gC = g_Cm + ((size_t)b * SEQLEN + s * LSEG) * DSTATE;
        for (int i = threadIdx.x * 4; i < LSEG * DSTATE; i += 128 * 4) {
            *reinterpret_cast<float4*>(&sB[i]) = *reinterpret_cast<const float4*>(&gB[i]);
            *reinterpret_cast<float4*>(&sC[i]) = *reinterpret_cast<const float4*>(&gC[i]);
        }
    }
    __syncthreads();

    float A[DSTATE];
    bool fast = true;
#pragma unroll
    for (int n = 0; n < DSTATE; n++) {
        A[n] = -expf(A_log[d * DSTATE + n]);
        fast = fast && (fabsf(A[n] - (float)(n + 1) * A[0]) <= 1e-4f * fabsf(A[n]));
    }
    const float Dp = D_param[d];

    if (fast) seg_scan_body<true >(b, d, s, A, Dp, sB, sC);
    else      seg_scan_body<false>(b, d, s, A, Dp, sB, sC);
}

// K4b: combine segments. Grid (64,4), 128 threads.
__global__ __launch_bounds__(128) void k4_combine() {
    const int b = blockIdx.x;
    const int d = blockIdx.y * 128 + threadIdx.x;

    float h[DSTATE];
#pragma unroll
    for (int n = 0; n < DSTATE; n++) h[n] = 0.f;
    float ysum = 0.f;

#pragma unroll
    for (int s = 0; s < SEG; s++) {
        size_t base = (((size_t)s * BATCH + b) * DINNER + d) * DSTATE;
        float dot = g_segc[((size_t)s * BATCH + b) * DINNER + d];
#pragma unroll
        for (int q = 0; q < DSTATE; q += 4) {
            float4 Wv = *reinterpret_cast<const float4*>(&g_segW[base + q]);
            float4 Pv = *reinterpret_cast<const float4*>(&g_segP[base + q]);
            float4 Vv = *reinterpret_cast<const float4*>(&g_segV[base + q]);
            dot = fmaf(Wv.x, h[q+0], dot);
            dot = fmaf(Wv.y, h[q+1], dot);
            dot = fmaf(Wv.z, h[q+2], dot);
            dot = fmaf(Wv.w, h[q+3], dot);
            h[q+0] = fmaf(Pv.x, h[q+0], Vv.x);
            h[q+1] = fmaf(Pv.y, h[q+1], Vv.y);
            h[q+2] = fmaf(Pv.z, h[q+2], Vv.z);
            h[q+3] = fmaf(Pv.w, h[q+3], Vv.w);
        }
        ysum += dot;
    }
    g_ybar[(size_t)b * DINNER + d] = ysum * (1.f / (float)SEQLEN);
}

// ---------------------------------------------------------------------------
// K5: head, warp-cooperative coalesced dots (R6-proven).
// ---------------------------------------------------------------------------
__device__ __forceinline__ float warp_dot(const float* __restrict__ wrow,
                                          const float* __restrict__ svec,
                                          int K, int lane) {
    float s = 0.f;
    for (int k = lane * 4; k < K; k += 128) {
        float4 wv = *reinterpret_cast<const float4*>(&wrow[k]);
        s = fmaf(svec[k + 0], wv.x, s);
        s = fmaf(svec[k + 1], wv.y, s);
        s = fmaf(svec[k + 2], wv.z, s);
        s = fmaf(svec[k + 3], wv.w, s);
    }
#pragma unroll
    for (int off = 16; off; off >>= 1) s += __shfl_down_sync(0xFFFFFFFFu, s, off);
    return s;
}

__global__ __launch_bounds__(256) void k5_head(const float* __restrict__ W_out,
                                               const float* __restrict__ W_outfc,
                                               const float* __restrict__ b_outfc,
                                               const float* __restrict__ W_mu,
                                               const float* __restrict__ b_mu,
                                               const float* __restrict__ W_sigma,
                                               const float* __restrict__ b_sigma,
                                               float* __restrict__ out) {
    const int b = blockIdx.x;
    const int tid = threadIdx.x;
    const int w = tid >> 5, lane = tid & 31;
    __shared__ float sy[DINNER];
    __shared__ float se[DMODEL];
    __shared__ float sxv[DIMIN];

    sy[tid] = g_ybar[(size_t)b * DINNER + tid];
    sy[tid + 256] = g_ybar[(size_t)b * DINNER + tid + 256];
    __syncthreads();

#pragma unroll
    for (int oi = 0; oi < 32; oi++) {
        const int o = w + oi * 8;
        float s = warp_dot(&W_out[o * DINNER], sy, DINNER, lane);
        if (lane == 0) se[o] = s;
    }
    __syncthreads();

#pragma unroll
    for (int oi = 0; oi < 32; oi++) {
        const int o = w + oi * 8;
        float s = warp_dot(&W_outfc[o * DMODEL], se, DMODEL, lane);
        if (lane == 0) {
            s += b_outfc[o];
            float t = tanhf(s);
            float xv = (t > 0.f) ? t : expm1f(t);
            sxv[o] = xv;
            out[(size_t)b * DIMIN + o] = xv;
        }
    }
    __syncthreads();

    float* out_mu    = out + BATCH * DIMIN;
    float* out_sigma = out + BATCH * DIMIN + BATCH * DIMOUT;
#pragma unroll
    for (int oi = 0; oi < 16; oi++) {
        const int o = w + oi * 8;
        if (o < DIMOUT) {
            float s = warp_dot(&W_mu[o * DIMIN], sxv, DIMIN, lane);
            if (lane == 0) out_mu[(size_t)b * DIMOUT + o] = s + b_mu[o];
        } else {
            const int o2 = o - DIMOUT;
            float s = warp_dot(&W_sigma[o2 * DIMIN], sxv, DIMIN, lane);
            if (lane == 0) {
                s += b_sigma[o2];
                float el = (s > 0.f) ? s : expm1f(s);
                out_sigma[(size_t)b * DIMOUT + o2] = el + 1.f + 1e-14f;
            }
        }
    }
}

// ---------------------------------------------------------------------------
extern "C" void kernel_launch(void* const* d_in, const int* in_sizes, int n_in,
                              void* d_out, int out_size) {
    const float* input   = (const float*)d_in[0];
    const float* W_in    = (const float*)d_in[1];
    const float* conv_w  = (const float*)d_in[2];
    const float* conv_b  = (const float*)d_in[3];
    const float* W_xproj = (const float*)d_in[4];
    const float* W_dt    = (const float*)d_in[5];
    const float* b_dt    = (const float*)d_in[6];
    const float* A_log   = (const float*)d_in[7];
    const float* D_param = (const float*)d_in[8];
    const float* W_out   = (const float*)d_in[9];
    const float* W_outfc = (const float*)d_in[10];
    const float* b_outfc = (const float*)d_in[11];
    const float* W_mu    = (const float*)d_in[12];
    const float* b_mu    = (const float*)d_in[13];
    const float* W_sigma = (const float*)d_in[14];
    const float* b_sigma = (const float*)d_in[15];
    float* out = (float*)d_out;

    k1_gemm<<<dim3(1024 / 128, BL / 128), 512>>>(input, W_in);
    k3_convproj<<<BL / K3ROWS, 512>>>(conv_w, conv_b, W_xproj, W_dt, b_dt);
    k4_seg<<<dim3(BATCH, DINNER / 128, SEG), 128>>>(A_log, D_param);
    k4_combine<<<dim3(BATCH, DINNER / 128), 128>>>();
    k5_head<<<BATCH, 256>>>(W_out, W_outfc, b_outfc, W_mu, b_mu, W_sigma, b_sigma, out);
}